// round 16
// baseline (speedup 1.0000x reference)
#include <cuda_runtime.h>
#include <cuda_bf16.h>
#include <cstdint>

// ---------------------------------------------------------------------------
// NGNN GCNConv: h = GCNConv(x) ; relu ; relu(h@Wfc^T+bfc) ; @Wfc2^T+bfc2
// N=100000, C=128, E=3.2M.
// Round 16: serial chain (streams rejected by harness); gather fused into
// the gemm23 prologue — agg never touches global memory.
// ---------------------------------------------------------------------------

#define MAX_N 100000
#define MAX_E 3200000
#define C 128
#define WROW 136   // bf16 elems per padded row (272B: 17x16B -> ldmatrix conflict-free)

__device__ __align__(256) float g_degw  [MAX_N];
__device__ __align__(256) float g_dinv  [MAX_N];
__device__ __align__(256) int   g_cnt   [MAX_N];
__device__ __align__(256) int   g_start [MAX_N];
__device__ __align__(256) int   g_cursor[MAX_N];
__device__ __align__(256) int   g_bsum  [512];
__device__ __align__(256) int   g_boff  [512];
__device__ __align__(256) int2  g_ebuf  [MAX_E];
__device__ __align__(256) float g_h     [(size_t)MAX_N * C];
// bf16 split weight images, padded row-major [j][k] (stride WROW)
__device__ __align__(256) __nv_bfloat16 g_Wimg[6][128 * WROW];
__device__ int g_is64;
__device__ int g_not1;

__device__ __forceinline__ uint32_t smem_u32(const void* p) {
    uint32_t a;
    asm("{ .reg .u64 t; cvta.to.shared.u64 t, %1; cvt.u32.u64 %0, t; }"
        : "=r"(a) : "l"(p));
    return a;
}
__device__ __forceinline__ void ldsm_x4(uint32_t& r0, uint32_t& r1,
                                        uint32_t& r2, uint32_t& r3, uint32_t a) {
    asm volatile("ldmatrix.sync.aligned.m8n8.x4.shared.b16 {%0,%1,%2,%3}, [%4];"
                 : "=r"(r0), "=r"(r1), "=r"(r2), "=r"(r3) : "r"(a));
}
__device__ __forceinline__ void mma_bf16(float* c, const uint32_t* a,
                                         uint32_t b0, uint32_t b1) {
    asm volatile(
        "mma.sync.aligned.m16n8k16.row.col.f32.bf16.bf16.f32 "
        "{%0,%1,%2,%3}, {%4,%5,%6,%7}, {%8,%9}, {%0,%1,%2,%3};"
        : "+f"(c[0]), "+f"(c[1]), "+f"(c[2]), "+f"(c[3])
        : "r"(a[0]), "r"(a[1]), "r"(a[2]), "r"(a[3]), "r"(b0), "r"(b1));
}
__device__ __forceinline__ void cp_async16(uint32_t dst, const void* src) {
    asm volatile("cp.async.cg.shared.global [%0], [%1], 16;"
                 :: "r"(dst), "l"(src) : "memory");
}
__device__ __forceinline__ void cp_async_wait_all() {
    asm volatile("cp.async.commit_group;\ncp.async.wait_group 0;" ::: "memory");
}
// bf16 hi/lo split of a float pair -> packed hi uint32, lo uint32
__device__ __forceinline__ void split2(float x, float y, uint32_t& hi, uint32_t& lo) {
    __nv_bfloat16 hx = __float2bfloat16(x), hy = __float2bfloat16(y);
    __nv_bfloat16 lx = __float2bfloat16(x - __bfloat162float(hx));
    __nv_bfloat16 ly = __float2bfloat16(y - __bfloat162float(hy));
    __nv_bfloat162 h = __halves2bfloat162(hx, hy);
    __nv_bfloat162 l = __halves2bfloat162(lx, ly);
    hi = *(unsigned*)&h; lo = *(unsigned*)&l;
}

__device__ __forceinline__ long long eidx(const void* ei, long long i) {
    return g_is64 ? ((const long long*)ei)[i]
                  : (long long)((const int*)ei)[i];
}

// ---------------------------------------------------------------------------
// Launch 1: zero scratch; block 0 detects edge_index dtype + clears g_not1.
// ---------------------------------------------------------------------------
__global__ void k_pre0(const unsigned int* __restrict__ ei32, int n, long long E) {
    int i = blockIdx.x * blockDim.x + threadIdx.x;
    if (i < n) { g_cnt[i] = 0; g_degw[i] = 0.0f; }
    if (blockIdx.x == 0) {
        __shared__ unsigned s_any;
        if (threadIdx.x == 0) { s_any = 0u; g_not1 = 0; }
        __syncthreads();
        long long lim = (E < 4096) ? E : 4096;
        unsigned any = 0u;
        for (long long j = threadIdx.x; j < lim; j += blockDim.x)
            any |= ei32[2 * j + 1];
        if (any) atomicOr(&s_any, 1u);
        __syncthreads();
        if (threadIdx.x == 0) g_is64 = (s_any == 0u) ? 1 : 0;
    }
}

// ---------------------------------------------------------------------------
// Launch 2: blocks [0,192): bf16-split weight images; [192,704): ew==1 check.
// ---------------------------------------------------------------------------
__global__ void k_prep(const float* __restrict__ W0,
                       const float* __restrict__ W1,
                       const float* __restrict__ W2,
                       const float* __restrict__ ew, long long E) {
    if (blockIdx.x < 192) {
        int idx = blockIdx.x * 256 + threadIdx.x;   // 0..49151
        int which = idx >> 14;
        int r = idx & 16383;
        const float* W = (which == 0) ? W0 : (which == 1) ? W1 : W2;
        int j = r >> 7, k = r & 127;
        float w = W[r];
        __nv_bfloat16 hi = __float2bfloat16(w);
        __nv_bfloat16 lo = __float2bfloat16(w - __bfloat162float(hi));
        g_Wimg[2 * which][j * WROW + k] = hi;
        g_Wimg[2 * which + 1][j * WROW + k] = lo;
    } else {
        int bad = 0;
        long long stride = 512LL * 256LL;
        for (long long i = (long long)(blockIdx.x - 192) * 256 + threadIdx.x;
             i < E; i += stride)
            if (ew[i] != 1.0f) bad = 1;
        if (bad) atomicOr(&g_not1, 1);
    }
}

// per-dst counts (+weighted degree only if some ew != 1)
__global__ void k_cnt(const void* __restrict__ ei,
                      const float* __restrict__ ew, long long E) {
    long long e = (long long)blockIdx.x * blockDim.x + threadIdx.x;
    if (e >= E) return;
    long long d = eidx(ei, E + e);
    atomicAdd(&g_cnt[d], 1);
    if (g_not1) atomicAdd(&g_degw[d], ew[e]);
}

// ---- exclusive prefix sum over g_cnt; dinv fused into stage C ----
__global__ void k_scanA(int n) {
    __shared__ int sm[256];
    int t = threadIdx.x;
    int i = blockIdx.x * 256 + t;
    sm[t] = (i < n) ? g_cnt[i] : 0;
    __syncthreads();
    for (int s = 128; s > 0; s >>= 1) {
        if (t < s) sm[t] += sm[t + s];
        __syncthreads();
    }
    if (t == 0) g_bsum[blockIdx.x] = sm[0];
}

__global__ void k_scanB(int nb) {
    __shared__ int sm[512];
    int t = threadIdx.x;
    int v = (t < nb) ? g_bsum[t] : 0;
    sm[t] = v;
    __syncthreads();
    for (int off = 1; off < 512; off <<= 1) {
        int x = (t >= off) ? sm[t - off] : 0;
        __syncthreads();
        sm[t] += x;
        __syncthreads();
    }
    if (t < nb) g_boff[t] = sm[t] - v;
}

__global__ void k_scanC(int n) {
    __shared__ int sm[256];
    int t = threadIdx.x;
    int i = blockIdx.x * 256 + t;
    int v = (i < n) ? g_cnt[i] : 0;
    sm[t] = v;
    __syncthreads();
    for (int off = 1; off < 256; off <<= 1) {
        int x = (t >= off) ? sm[t - off] : 0;
        __syncthreads();
        sm[t] += x;
        __syncthreads();
    }
    if (i < n) {
        int start = g_boff[blockIdx.x] + sm[t] - v;
        g_start[i] = start;
        g_cursor[i] = start;
        float deg = (g_not1 ? g_degw[i] : (float)v) + 1.0f;
        g_dinv[i] = (deg > 0.0f) ? rsqrtf(deg) : 0.0f;
    }
}

// scatter {src, norm} into dst-ordered buckets
__global__ void k_scatter(const void* __restrict__ ei,
                          const float* __restrict__ ew, long long E) {
    long long e = (long long)blockIdx.x * blockDim.x + threadIdx.x;
    if (e >= E) return;
    long long s = eidx(ei, e);
    long long d = eidx(ei, E + e);
    float nm = g_dinv[s] * g_dinv[d];
    if (g_not1) nm *= ew[e];
    int pos = atomicAdd(&g_cursor[d], 1);
    g_ebuf[pos] = make_int2((int)s, __float_as_int(nm));
}

// ---------------------------------------------------------------------------
// GEMM1: 64x128 tile, 256 thr, 2 CTAs/SM (R13 config).
// ---------------------------------------------------------------------------
#define A_IMG_B (64 * WROW * 2)                  // 17408 bytes
#define W_IMG_B (128 * WROW * 2)                 // 34816 bytes
#define MG_AHI  0
#define MG_ALO  (MG_AHI + A_IMG_B)
#define MG_WHI  (MG_ALO + A_IMG_B)
#define MG_WLO  (MG_WHI + W_IMG_B)
#define MG_SMEM (MG_WLO + W_IMG_B)               // 104448 bytes

__global__ __launch_bounds__(256, 2) void k_mgemm1(
    const float* __restrict__ A,
    const __nv_bfloat16* __restrict__ Whi_img,
    const __nv_bfloat16* __restrict__ Wlo_img,
    float* __restrict__ Cout, int n) {
    extern __shared__ char smem[];
    uint32_t sb = smem_u32(smem);
    int tid = threadIdx.x;
    int wid = tid >> 5, lane = tid & 31;
    int row0 = blockIdx.x * 64;

    {
        const char* sh = (const char*)Whi_img;
        const char* sl = (const char*)Wlo_img;
        for (int i = tid; i < W_IMG_B / 16; i += 256) {
            cp_async16(sb + MG_WHI + i * 16, sh + i * 16);
            cp_async16(sb + MG_WLO + i * 16, sl + i * 16);
        }
    }

    for (int idx = tid; idx < 2048; idx += 256) {
        int r = idx >> 5, q = idx & 31;
        int row = row0 + r, k0 = q * 4;
        float4 v = make_float4(0.f, 0.f, 0.f, 0.f);
        if (row < n) v = *(const float4*)&A[(long long)row * C + k0];
        uint32_t h01, l01, h23, l23;
        split2(v.x, v.y, h01, l01);
        split2(v.z, v.w, h23, l23);
        uint32_t off = (uint32_t)(r * WROW + k0) * 2;
        *(uint2*)(smem + MG_AHI + off) = make_uint2(h01, h23);
        *(uint2*)(smem + MG_ALO + off) = make_uint2(l01, l23);
    }
    cp_async_wait_all();
    __syncthreads();

    int mrow0 = (wid >> 2) * 32;
    int ncol0 = (wid & 3) * 32;
    int li = lane & 7, seg = lane >> 3;

    float acc[2][4][4];
#pragma unroll
    for (int m = 0; m < 2; m++)
#pragma unroll
        for (int nb = 0; nb < 4; nb++)
#pragma unroll
            for (int p = 0; p < 4; p++) acc[m][nb][p] = 0.0f;

    uint32_t aoff = (uint32_t)((mrow0 + li + (seg & 1) * 8) * WROW
                               + (seg >> 1) * 8) * 2;
    uint32_t boff = (uint32_t)((ncol0 + li + (seg >> 1) * 8) * WROW
                               + (seg & 1) * 8) * 2;

#pragma unroll 1
    for (int p = 0; p < 3; p++) {
        uint32_t abase = sb + (p == 2 ? MG_ALO : MG_AHI);
        uint32_t wbase = sb + (p == 1 ? MG_WLO : MG_WHI);
#pragma unroll
        for (int kb = 0; kb < 8; kb++) {
            uint32_t kadd = (uint32_t)(kb * 16) * 2;
            uint32_t a0[4], a1[4];
            ldsm_x4(a0[0], a0[1], a0[2], a0[3], abase + aoff + kadd);
            ldsm_x4(a1[0], a1[1], a1[2], a1[3],
                    abase + aoff + kadd + (uint32_t)(16 * WROW * 2));
            uint32_t b[4][2];
#pragma unroll
            for (int np = 0; np < 2; np++) {
                uint32_t r0, r1, r2, r3;
                ldsm_x4(r0, r1, r2, r3,
                        wbase + boff + kadd + (uint32_t)(np * 16 * WROW * 2));
                b[2 * np][0] = r0; b[2 * np][1] = r1;
                b[2 * np + 1][0] = r2; b[2 * np + 1][1] = r3;
            }
#pragma unroll
            for (int nb = 0; nb < 4; nb++) {
                mma_bf16(acc[0][nb], a0, b[nb][0], b[nb][1]);
                mma_bf16(acc[1][nb], a1, b[nb][0], b[nb][1]);
            }
        }
    }

#pragma unroll
    for (int m = 0; m < 2; m++) {
        int r_lo = row0 + mrow0 + m * 16 + (lane >> 2);
        int r_hi = r_lo + 8;
#pragma unroll
        for (int nb = 0; nb < 4; nb++) {
            int col = ncol0 + nb * 8 + (lane & 3) * 2;
            if (r_lo < n) *(float2*)&Cout[(long long)r_lo * C + col] =
                make_float2(acc[m][nb][0], acc[m][nb][1]);
            if (r_hi < n) *(float2*)&Cout[(long long)r_hi * C + col] =
                make_float2(acc[m][nb][2], acc[m][nb][3]);
        }
    }
}

// ---------------------------------------------------------------------------
// Fused GATHER + GEMM2 + GEMM3:
//   agg = gather(h) ; out = relu(relu(agg+bc)@Wf^T + bf) @ W2^T + b2.
// CTA 128x128, 512 thr. The 16 warps gather 8 rows each (edge loop), apply
// bc+relu in registers, and write bf16 hi/lo straight into A smem. agg never
// exists in global memory. W images cp.async'd under the gather phase.
// ---------------------------------------------------------------------------
#define F_AHI  0
#define F_ALO  (F_AHI + W_IMG_B)
#define F_W1HI (F_ALO + W_IMG_B)
#define F_W1LO (F_W1HI + W_IMG_B)
#define F_W2HI (F_W1LO + W_IMG_B)
#define F_W2LO (F_W2HI + W_IMG_B)
#define F_SMEM (F_W2LO + W_IMG_B)                // 208896 bytes

__global__ __launch_bounds__(512, 1) void k_gg23(
    const __nv_bfloat16* __restrict__ W1hi, const __nv_bfloat16* __restrict__ W1lo,
    const __nv_bfloat16* __restrict__ W2hi, const __nv_bfloat16* __restrict__ W2lo,
    const float* __restrict__ bc, const float* __restrict__ bf,
    const float* __restrict__ b2,
    float* __restrict__ Cout, int n) {
    extern __shared__ char smem[];
    uint32_t sb = smem_u32(smem);
    int tid = threadIdx.x;
    int wid = tid >> 5, lane = tid & 31;
    int row0 = blockIdx.x * 128;

    // W images fetched async under the gather phase
    for (int i = tid; i < W_IMG_B / 16; i += 512) {
        cp_async16(sb + F_W1HI + i * 16, (const char*)W1hi + i * 16);
        cp_async16(sb + F_W1LO + i * 16, (const char*)W1lo + i * 16);
        cp_async16(sb + F_W2HI + i * 16, (const char*)W2hi + i * 16);
        cp_async16(sb + F_W2LO + i * 16, (const char*)W2lo + i * 16);
    }

    // ---- gather phase: warp wid gathers rows wid*8 .. wid*8+7 ----
    {
        float4 bc4 = *(const float4*)&bc[lane * 4];
#pragma unroll 1
        for (int j = 0; j < 8; j++) {
            int r = wid * 8 + j;
            int w = row0 + r;
            float4 acc = make_float4(0.f, 0.f, 0.f, 0.f);
            if (w < n) {
                int beg = g_start[w];
                int num = g_cnt[w];
                float di = g_dinv[w];
                float self = di * di;
                float4 hv = *(const float4*)&g_h[(long long)w * C + lane * 4];
                acc = make_float4(hv.x * self, hv.y * self,
                                  hv.z * self, hv.w * self);
                int i = 0;
                for (; i + 4 <= num; i += 4) {
                    int2 e0 = g_ebuf[beg + i];
                    int2 e1 = g_ebuf[beg + i + 1];
                    int2 e2 = g_ebuf[beg + i + 2];
                    int2 e3 = g_ebuf[beg + i + 3];
                    float4 h0 = *(const float4*)&g_h[(long long)e0.x * C + lane * 4];
                    float4 h1 = *(const float4*)&g_h[(long long)e1.x * C + lane * 4];
                    float4 h2 = *(const float4*)&g_h[(long long)e2.x * C + lane * 4];
                    float4 h3 = *(const float4*)&g_h[(long long)e3.x * C + lane * 4];
                    float n0 = __int_as_float(e0.y), n1 = __int_as_float(e1.y);
                    float n2 = __int_as_float(e2.y), n3 = __int_as_float(e3.y);
                    acc.x += n0 * h0.x; acc.y += n0 * h0.y;
                    acc.z += n0 * h0.z; acc.w += n0 * h0.w;
                    acc.x += n1 * h1.x; acc.y += n1 * h1.y;
                    acc.z += n1 * h1.z; acc.w += n1 * h1.w;
                    acc.x += n2 * h2.x; acc.y += n2 * h2.y;
                    acc.z += n2 * h2.z; acc.w += n2 * h2.w;
                    acc.x += n3 * h3.x; acc.y += n3 * h3.y;
                    acc.z += n3 * h3.z; acc.w += n3 * h3.w;
                }
                for (; i < num; i++) {
                    int2 e0 = g_ebuf[beg + i];
                    float4 h0 = *(const float4*)&g_h[(long long)e0.x * C + lane * 4];
                    float n0 = __int_as_float(e0.y);
                    acc.x += n0 * h0.x; acc.y += n0 * h0.y;
                    acc.z += n0 * h0.z; acc.w += n0 * h0.w;
                }
                // bias + relu (input to GEMM2)
                acc.x = fmaxf(acc.x + bc4.x, 0.0f);
                acc.y = fmaxf(acc.y + bc4.y, 0.0f);
                acc.z = fmaxf(acc.z + bc4.z, 0.0f);
                acc.w = fmaxf(acc.w + bc4.w, 0.0f);
            }
            uint32_t h01, l01, h23, l23;
            split2(acc.x, acc.y, h01, l01);
            split2(acc.z, acc.w, h23, l23);
            uint32_t off = (uint32_t)(r * WROW + lane * 4) * 2;
            *(uint2*)(smem + F_AHI + off) = make_uint2(h01, h23);
            *(uint2*)(smem + F_ALO + off) = make_uint2(l01, l23);
        }
    }
    cp_async_wait_all();
    __syncthreads();

    int mrow0 = (wid >> 2) * 32;        // 0,32,64,96
    int ncol0 = (wid & 3) * 32;         // 0,32,64,96
    int li = lane & 7, seg = lane >> 3;

    uint32_t aoff = (uint32_t)((mrow0 + li + (seg & 1) * 8) * WROW
                               + (seg >> 1) * 8) * 2;
    uint32_t boff = (uint32_t)((ncol0 + li + (seg >> 1) * 8) * WROW
                               + (seg & 1) * 8) * 2;

    float acc[2][4][4];

    // ---------------- phase 1: h2c = A-split @ Wf ----------------
#pragma unroll
    for (int m = 0; m < 2; m++)
#pragma unroll
        for (int nb = 0; nb < 4; nb++)
#pragma unroll
            for (int p = 0; p < 4; p++) acc[m][nb][p] = 0.0f;

#pragma unroll 1
    for (int p = 0; p < 3; p++) {
        uint32_t abase = sb + (p == 2 ? F_ALO : F_AHI);
        uint32_t wbase = sb + (p == 1 ? F_W1LO : F_W1HI);
#pragma unroll
        for (int kb = 0; kb < 8; kb++) {
            uint32_t kadd = (uint32_t)(kb * 16) * 2;
            uint32_t a0[4], a1[4];
            ldsm_x4(a0[0], a0[1], a0[2], a0[3], abase + aoff + kadd);
            ldsm_x4(a1[0], a1[1], a1[2], a1[3],
                    abase + aoff + kadd + (uint32_t)(16 * WROW * 2));
            uint32_t b[4][2];
#pragma unroll
            for (int np = 0; np < 2; np++) {
                uint32_t r0, r1, r2, r3;
                ldsm_x4(r0, r1, r2, r3,
                        wbase + boff + kadd + (uint32_t)(np * 16 * WROW * 2));
                b[2 * np][0] = r0; b[2 * np][1] = r1;
                b[2 * np + 1][0] = r2; b[2 * np + 1][1] = r3;
            }
#pragma unroll
            for (int nb = 0; nb < 4; nb++) {
                mma_bf16(acc[0][nb], a0, b[nb][0], b[nb][1]);
                mma_bf16(acc[1][nb], a1, b[nb][0], b[nb][1]);
            }
        }
    }
    __syncthreads();   // all phase-1 smem reads done before overwriting A

    // h2 = relu(acc + bf) -> bf16 hi/lo back into A smem (warp owns its patch)
    {
        float2 mb[4];
#pragma unroll
        for (int nb = 0; nb < 4; nb++) {
            int col = ncol0 + nb * 8 + (lane & 3) * 2;
            mb[nb] = *(const float2*)&bf[col];
        }
#pragma unroll
        for (int m = 0; m < 2; m++) {
            int r_lo = mrow0 + m * 16 + (lane >> 2);   // local rows
            int r_hi = r_lo + 8;
#pragma unroll
            for (int nb = 0; nb < 4; nb++) {
                int col = ncol0 + nb * 8 + (lane & 3) * 2;
                float x0 = fmaxf(acc[m][nb][0] + mb[nb].x, 0.0f);
                float y0 = fmaxf(acc[m][nb][1] + mb[nb].y, 0.0f);
                float x1 = fmaxf(acc[m][nb][2] + mb[nb].x, 0.0f);
                float y1 = fmaxf(acc[m][nb][3] + mb[nb].y, 0.0f);
                uint32_t h0, l0, h1, l1;
                split2(x0, y0, h0, l0);
                split2(x1, y1, h1, l1);
                uint32_t o0 = (uint32_t)(r_lo * WROW + col) * 2;
                uint32_t o1 = (uint32_t)(r_hi * WROW + col) * 2;
                *(uint32_t*)(smem + F_AHI + o0) = h0;
                *(uint32_t*)(smem + F_ALO + o0) = l0;
                *(uint32_t*)(smem + F_AHI + o1) = h1;
                *(uint32_t*)(smem + F_ALO + o1) = l1;
            }
        }
    }
    __syncthreads();

    // ---------------- phase 2: out = h2-split @ W2 ----------------
#pragma unroll
    for (int m = 0; m < 2; m++)
#pragma unroll
        for (int nb = 0; nb < 4; nb++)
#pragma unroll
            for (int p = 0; p < 4; p++) acc[m][nb][p] = 0.0f;

#pragma unroll 1
    for (int p = 0; p < 3; p++) {
        uint32_t abase = sb + (p == 2 ? F_ALO : F_AHI);
        uint32_t wbase = sb + (p == 1 ? F_W2LO : F_W2HI);
#pragma unroll
        for (int kb = 0; kb < 8; kb++) {
            uint32_t kadd = (uint32_t)(kb * 16) * 2;
            uint32_t a0[4], a1[4];
            ldsm_x4(a0[0], a0[1], a0[2], a0[3], abase + aoff + kadd);
            ldsm_x4(a1[0], a1[1], a1[2], a1[3],
                    abase + aoff + kadd + (uint32_t)(16 * WROW * 2));
            uint32_t b[4][2];
#pragma unroll
            for (int np = 0; np < 2; np++) {
                uint32_t r0, r1, r2, r3;
                ldsm_x4(r0, r1, r2, r3,
                        wbase + boff + kadd + (uint32_t)(np * 16 * WROW * 2));
                b[2 * np][0] = r0; b[2 * np][1] = r1;
                b[2 * np + 1][0] = r2; b[2 * np + 1][1] = r3;
            }
#pragma unroll
            for (int nb = 0; nb < 4; nb++) {
                mma_bf16(acc[0][nb], a0, b[nb][0], b[nb][1]);
                mma_bf16(acc[1][nb], a1, b[nb][0], b[nb][1]);
            }
        }
    }

    // final epilogue: + b2, store to global
    {
        float2 pb[4];
#pragma unroll
        for (int nb = 0; nb < 4; nb++) {
            int col = ncol0 + nb * 8 + (lane & 3) * 2;
            pb[nb] = *(const float2*)&b2[col];
        }
#pragma unroll
        for (int m = 0; m < 2; m++) {
            int r_lo = row0 + mrow0 + m * 16 + (lane >> 2);
            int r_hi = r_lo + 8;
#pragma unroll
            for (int nb = 0; nb < 4; nb++) {
                int col = ncol0 + nb * 8 + (lane & 3) * 2;
                if (r_lo < n) *(float2*)&Cout[(long long)r_lo * C + col] =
                    make_float2(acc[m][nb][0] + pb[nb].x, acc[m][nb][1] + pb[nb].y);
                if (r_hi < n) *(float2*)&Cout[(long long)r_hi * C + col] =
                    make_float2(acc[m][nb][2] + pb[nb].x, acc[m][nb][3] + pb[nb].y);
            }
        }
    }
}

// ---------------------------------------------------------------------------
extern "C" void kernel_launch(void* const* d_in, const int* in_sizes, int n_in,
                              void* d_out, int out_size) {
    const float* x  = (const float*)d_in[0];
    const void*  ei = d_in[1];
    const float* ew = (const float*)d_in[2];
    const float* Wc = (const float*)d_in[3];
    const float* bc = (const float*)d_in[4];
    const float* Wf = (const float*)d_in[5];
    const float* bf = (const float*)d_in[6];
    const float* W2 = (const float*)d_in[7];
    const float* b2 = (const float*)d_in[8];
    float* out = (float*)d_out;

    int n = in_sizes[0] / C;
    long long E = in_sizes[2];
    int nb = (n + 255) / 256;
    int g1_blocks = (n + 63) / 64;
    int g23_blocks = (n + 127) / 128;
    unsigned eblocks = (unsigned)((E + 255) / 256);

    cudaFuncSetAttribute(k_mgemm1,
                         cudaFuncAttributeMaxDynamicSharedMemorySize, MG_SMEM);
    cudaFuncSetAttribute(k_gg23,
                         cudaFuncAttributeMaxDynamicSharedMemorySize, F_SMEM);

    float* g_h_p;   cudaGetSymbolAddress((void**)&g_h_p,   g_h);
    __nv_bfloat16* g_Wimg_p;
    cudaGetSymbolAddress((void**)&g_Wimg_p, g_Wimg);
    const int IMG_E = 128 * WROW;
    const __nv_bfloat16* WcHi = g_Wimg_p;
    const __nv_bfloat16* WcLo = g_Wimg_p + IMG_E;
    const __nv_bfloat16* WfHi = g_Wimg_p + 2 * IMG_E;
    const __nv_bfloat16* WfLo = g_Wimg_p + 3 * IMG_E;
    const __nv_bfloat16* W2Hi = g_Wimg_p + 4 * IMG_E;
    const __nv_bfloat16* W2Lo = g_Wimg_p + 5 * IMG_E;

    // 1. zero scratch + dtype detect
    k_pre0<<<nb, 256>>>((const unsigned int*)ei, n, E);
    // 2. bf16-split weight images + edge_weight==1 check
    k_prep<<<192 + 512, 256>>>(Wc, Wf, W2, ew, E);
    // 3. per-dst counts (+conditional weighted degree)
    k_cnt<<<eblocks, 256>>>(ei, ew, E);
    // 4. h = x @ Wc^T        <-- 4th launch: ncu profiles this one
    k_mgemm1<<<g1_blocks, 256, MG_SMEM>>>(x, WcHi, WcLo, g_h_p, n);
    // 5-7. exclusive prefix sum (+dinv fused)
    k_scanA<<<nb, 256>>>(n);
    k_scanB<<<1, 512>>>(nb);
    k_scanC<<<nb, 256>>>(n);
    // 8. scatter edges into dst buckets
    k_scatter<<<eblocks, 256>>>(ei, ew, E);
    // 9. fused: gather + out = relu(relu(agg+bc)@Wf^T + bf) @ W2^T + b2
    k_gg23<<<g23_blocks, 512, F_SMEM>>>(
        WfHi, WfLo, W2Hi, W2Lo, bc, bf, b2, out, n);
}

// round 17
// speedup vs baseline: 1.1875x; 1.1875x over previous
#include <cuda_runtime.h>
#include <cuda_bf16.h>
#include <cuda_fp16.h>
#include <cstdint>

// ---------------------------------------------------------------------------
// NGNN GCNConv: h = GCNConv(x) ; relu ; relu(h@Wfc^T+bfc) ; @Wfc2^T+bfc2
// N=100000, C=128, E=3.2M.
// Round 17: R14 structure (standalone gather at full occupancy + fused
// gemm23) with h stored in FP16 — halves the gather's LTS traffic.
// ---------------------------------------------------------------------------

#define MAX_N 100000
#define MAX_E 3200000
#define C 128
#define WROW 136   // bf16 elems per padded row (272B: 17x16B -> ldmatrix conflict-free)

__device__ __align__(256) float  g_degw  [MAX_N];
__device__ __align__(256) float  g_dinv  [MAX_N];
__device__ __align__(256) int    g_cnt   [MAX_N];
__device__ __align__(256) int    g_start [MAX_N];
__device__ __align__(256) int    g_cursor[MAX_N];
__device__ __align__(256) int    g_bsum  [512];
__device__ __align__(256) int    g_boff  [512];
__device__ __align__(256) int2   g_ebuf  [MAX_E];
__device__ __align__(256) __half g_h     [(size_t)MAX_N * C];   // fp16 h
__device__ __align__(256) float  g_agg   [(size_t)MAX_N * C];
// bf16 split weight images, padded row-major [j][k] (stride WROW)
__device__ __align__(256) __nv_bfloat16 g_Wimg[6][128 * WROW];
__device__ int g_is64;
__device__ int g_not1;

__device__ __forceinline__ uint32_t smem_u32(const void* p) {
    uint32_t a;
    asm("{ .reg .u64 t; cvta.to.shared.u64 t, %1; cvt.u32.u64 %0, t; }"
        : "=r"(a) : "l"(p));
    return a;
}
__device__ __forceinline__ void ldsm_x4(uint32_t& r0, uint32_t& r1,
                                        uint32_t& r2, uint32_t& r3, uint32_t a) {
    asm volatile("ldmatrix.sync.aligned.m8n8.x4.shared.b16 {%0,%1,%2,%3}, [%4];"
                 : "=r"(r0), "=r"(r1), "=r"(r2), "=r"(r3) : "r"(a));
}
__device__ __forceinline__ void mma_bf16(float* c, const uint32_t* a,
                                         uint32_t b0, uint32_t b1) {
    asm volatile(
        "mma.sync.aligned.m16n8k16.row.col.f32.bf16.bf16.f32 "
        "{%0,%1,%2,%3}, {%4,%5,%6,%7}, {%8,%9}, {%0,%1,%2,%3};"
        : "+f"(c[0]), "+f"(c[1]), "+f"(c[2]), "+f"(c[3])
        : "r"(a[0]), "r"(a[1]), "r"(a[2]), "r"(a[3]), "r"(b0), "r"(b1));
}
__device__ __forceinline__ void cp_async16(uint32_t dst, const void* src) {
    asm volatile("cp.async.cg.shared.global [%0], [%1], 16;"
                 :: "r"(dst), "l"(src) : "memory");
}
__device__ __forceinline__ void cp_async_wait_all() {
    asm volatile("cp.async.commit_group;\ncp.async.wait_group 0;" ::: "memory");
}
// bf16 hi/lo split of a float pair -> packed hi uint32, lo uint32
__device__ __forceinline__ void split2(float x, float y, uint32_t& hi, uint32_t& lo) {
    __nv_bfloat16 hx = __float2bfloat16(x), hy = __float2bfloat16(y);
    __nv_bfloat16 lx = __float2bfloat16(x - __bfloat162float(hx));
    __nv_bfloat16 ly = __float2bfloat16(y - __bfloat162float(hy));
    __nv_bfloat162 h = __halves2bfloat162(hx, hy);
    __nv_bfloat162 l = __halves2bfloat162(lx, ly);
    hi = *(unsigned*)&h; lo = *(unsigned*)&l;
}
// load 4 fp16 h channels -> float4 (8B load)
__device__ __forceinline__ float4 ldh4(long long idx) {
    uint2 r = *(const uint2*)&g_h[idx];
    __half2 a = *(__half2*)&r.x, b = *(__half2*)&r.y;
    float2 f0 = __half22float2(a), f1 = __half22float2(b);
    return make_float4(f0.x, f0.y, f1.x, f1.y);
}

__device__ __forceinline__ long long eidx(const void* ei, long long i) {
    return g_is64 ? ((const long long*)ei)[i]
                  : (long long)((const int*)ei)[i];
}

// ---------------------------------------------------------------------------
// Launch 1: zero scratch; block 0 detects edge_index dtype + clears g_not1.
// ---------------------------------------------------------------------------
__global__ void k_pre0(const unsigned int* __restrict__ ei32, int n, long long E) {
    int i = blockIdx.x * blockDim.x + threadIdx.x;
    if (i < n) { g_cnt[i] = 0; g_degw[i] = 0.0f; }
    if (blockIdx.x == 0) {
        __shared__ unsigned s_any;
        if (threadIdx.x == 0) { s_any = 0u; g_not1 = 0; }
        __syncthreads();
        long long lim = (E < 4096) ? E : 4096;
        unsigned any = 0u;
        for (long long j = threadIdx.x; j < lim; j += blockDim.x)
            any |= ei32[2 * j + 1];
        if (any) atomicOr(&s_any, 1u);
        __syncthreads();
        if (threadIdx.x == 0) g_is64 = (s_any == 0u) ? 1 : 0;
    }
}

// ---------------------------------------------------------------------------
// Launch 2: blocks [0,192): bf16-split weight images; [192,704): ew==1 check.
// ---------------------------------------------------------------------------
__global__ void k_prep(const float* __restrict__ W0,
                       const float* __restrict__ W1,
                       const float* __restrict__ W2,
                       const float* __restrict__ ew, long long E) {
    if (blockIdx.x < 192) {
        int idx = blockIdx.x * 256 + threadIdx.x;   // 0..49151
        int which = idx >> 14;
        int r = idx & 16383;
        const float* W = (which == 0) ? W0 : (which == 1) ? W1 : W2;
        int j = r >> 7, k = r & 127;
        float w = W[r];
        __nv_bfloat16 hi = __float2bfloat16(w);
        __nv_bfloat16 lo = __float2bfloat16(w - __bfloat162float(hi));
        g_Wimg[2 * which][j * WROW + k] = hi;
        g_Wimg[2 * which + 1][j * WROW + k] = lo;
    } else {
        int bad = 0;
        long long stride = 512LL * 256LL;
        for (long long i = (long long)(blockIdx.x - 192) * 256 + threadIdx.x;
             i < E; i += stride)
            if (ew[i] != 1.0f) bad = 1;
        if (bad) atomicOr(&g_not1, 1);
    }
}

// per-dst counts (+weighted degree only if some ew != 1)
__global__ void k_cnt(const void* __restrict__ ei,
                      const float* __restrict__ ew, long long E) {
    long long e = (long long)blockIdx.x * blockDim.x + threadIdx.x;
    if (e >= E) return;
    long long d = eidx(ei, E + e);
    atomicAdd(&g_cnt[d], 1);
    if (g_not1) atomicAdd(&g_degw[d], ew[e]);
}

// ---- exclusive prefix sum over g_cnt; dinv fused into stage C ----
__global__ void k_scanA(int n) {
    __shared__ int sm[256];
    int t = threadIdx.x;
    int i = blockIdx.x * 256 + t;
    sm[t] = (i < n) ? g_cnt[i] : 0;
    __syncthreads();
    for (int s = 128; s > 0; s >>= 1) {
        if (t < s) sm[t] += sm[t + s];
        __syncthreads();
    }
    if (t == 0) g_bsum[blockIdx.x] = sm[0];
}

__global__ void k_scanB(int nb) {
    __shared__ int sm[512];
    int t = threadIdx.x;
    int v = (t < nb) ? g_bsum[t] : 0;
    sm[t] = v;
    __syncthreads();
    for (int off = 1; off < 512; off <<= 1) {
        int x = (t >= off) ? sm[t - off] : 0;
        __syncthreads();
        sm[t] += x;
        __syncthreads();
    }
    if (t < nb) g_boff[t] = sm[t] - v;
}

__global__ void k_scanC(int n) {
    __shared__ int sm[256];
    int t = threadIdx.x;
    int i = blockIdx.x * 256 + t;
    int v = (i < n) ? g_cnt[i] : 0;
    sm[t] = v;
    __syncthreads();
    for (int off = 1; off < 256; off <<= 1) {
        int x = (t >= off) ? sm[t - off] : 0;
        __syncthreads();
        sm[t] += x;
        __syncthreads();
    }
    if (i < n) {
        int start = g_boff[blockIdx.x] + sm[t] - v;
        g_start[i] = start;
        g_cursor[i] = start;
        float deg = (g_not1 ? g_degw[i] : (float)v) + 1.0f;
        g_dinv[i] = (deg > 0.0f) ? rsqrtf(deg) : 0.0f;
    }
}

// scatter {src, norm} into dst-ordered buckets
__global__ void k_scatter(const void* __restrict__ ei,
                          const float* __restrict__ ew, long long E) {
    long long e = (long long)blockIdx.x * blockDim.x + threadIdx.x;
    if (e >= E) return;
    long long s = eidx(ei, e);
    long long d = eidx(ei, E + e);
    float nm = g_dinv[s] * g_dinv[d];
    if (g_not1) nm *= ew[e];
    int pos = atomicAdd(&g_cursor[d], 1);
    g_ebuf[pos] = make_int2((int)s, __float_as_int(nm));
}

// ---------------------------------------------------------------------------
// Gather: one warp per dst node, lane = 4 channels (fp16 h, 8B loads).
// ---------------------------------------------------------------------------
__global__ void k_gather(int n) {
    int w = (int)(((long long)blockIdx.x * blockDim.x + threadIdx.x) >> 5);
    if (w >= n) return;
    int lane = threadIdx.x & 31;
    int beg = g_start[w];
    int num = g_cnt[w];
    float di = g_dinv[w];
    float self = di * di;

    float4 hv = ldh4((long long)w * C + lane * 4);
    float4 acc = make_float4(hv.x * self, hv.y * self, hv.z * self, hv.w * self);

    int i = 0;
    for (; i + 4 <= num; i += 4) {
        int2 e0 = g_ebuf[beg + i];
        int2 e1 = g_ebuf[beg + i + 1];
        int2 e2 = g_ebuf[beg + i + 2];
        int2 e3 = g_ebuf[beg + i + 3];
        float4 h0 = ldh4((long long)e0.x * C + lane * 4);
        float4 h1 = ldh4((long long)e1.x * C + lane * 4);
        float4 h2 = ldh4((long long)e2.x * C + lane * 4);
        float4 h3 = ldh4((long long)e3.x * C + lane * 4);
        float n0 = __int_as_float(e0.y), n1 = __int_as_float(e1.y);
        float n2 = __int_as_float(e2.y), n3 = __int_as_float(e3.y);
        acc.x += n0 * h0.x; acc.y += n0 * h0.y; acc.z += n0 * h0.z; acc.w += n0 * h0.w;
        acc.x += n1 * h1.x; acc.y += n1 * h1.y; acc.z += n1 * h1.z; acc.w += n1 * h1.w;
        acc.x += n2 * h2.x; acc.y += n2 * h2.y; acc.z += n2 * h2.z; acc.w += n2 * h2.w;
        acc.x += n3 * h3.x; acc.y += n3 * h3.y; acc.z += n3 * h3.z; acc.w += n3 * h3.w;
    }
    for (; i < num; i++) {
        int2 e0 = g_ebuf[beg + i];
        float4 h0 = ldh4((long long)e0.x * C + lane * 4);
        float n0 = __int_as_float(e0.y);
        acc.x += n0 * h0.x; acc.y += n0 * h0.y; acc.z += n0 * h0.z; acc.w += n0 * h0.w;
    }
    *(float4*)&g_agg[(long long)w * C + lane * 4] = acc;
}

// ---------------------------------------------------------------------------
// GEMM1: 64x128 tile, 256 thr, 2 CTAs/SM; writes h in FP16.
// ---------------------------------------------------------------------------
#define A_IMG_B (64 * WROW * 2)                  // 17408 bytes
#define W_IMG_B (128 * WROW * 2)                 // 34816 bytes
#define MG_AHI  0
#define MG_ALO  (MG_AHI + A_IMG_B)
#define MG_WHI  (MG_ALO + A_IMG_B)
#define MG_WLO  (MG_WHI + W_IMG_B)
#define MG_SMEM (MG_WLO + W_IMG_B)               // 104448 bytes

__global__ __launch_bounds__(256, 2) void k_mgemm1(
    const float* __restrict__ A,
    const __nv_bfloat16* __restrict__ Whi_img,
    const __nv_bfloat16* __restrict__ Wlo_img,
    __half* __restrict__ Cout, int n) {
    extern __shared__ char smem[];
    uint32_t sb = smem_u32(smem);
    int tid = threadIdx.x;
    int wid = tid >> 5, lane = tid & 31;
    int row0 = blockIdx.x * 64;

    {
        const char* sh = (const char*)Whi_img;
        const char* sl = (const char*)Wlo_img;
        for (int i = tid; i < W_IMG_B / 16; i += 256) {
            cp_async16(sb + MG_WHI + i * 16, sh + i * 16);
            cp_async16(sb + MG_WLO + i * 16, sl + i * 16);
        }
    }

    for (int idx = tid; idx < 2048; idx += 256) {
        int r = idx >> 5, q = idx & 31;
        int row = row0 + r, k0 = q * 4;
        float4 v = make_float4(0.f, 0.f, 0.f, 0.f);
        if (row < n) v = *(const float4*)&A[(long long)row * C + k0];
        uint32_t h01, l01, h23, l23;
        split2(v.x, v.y, h01, l01);
        split2(v.z, v.w, h23, l23);
        uint32_t off = (uint32_t)(r * WROW + k0) * 2;
        *(uint2*)(smem + MG_AHI + off) = make_uint2(h01, h23);
        *(uint2*)(smem + MG_ALO + off) = make_uint2(l01, l23);
    }
    cp_async_wait_all();
    __syncthreads();

    int mrow0 = (wid >> 2) * 32;
    int ncol0 = (wid & 3) * 32;
    int li = lane & 7, seg = lane >> 3;

    float acc[2][4][4];
#pragma unroll
    for (int m = 0; m < 2; m++)
#pragma unroll
        for (int nb = 0; nb < 4; nb++)
#pragma unroll
            for (int p = 0; p < 4; p++) acc[m][nb][p] = 0.0f;

    uint32_t aoff = (uint32_t)((mrow0 + li + (seg & 1) * 8) * WROW
                               + (seg >> 1) * 8) * 2;
    uint32_t boff = (uint32_t)((ncol0 + li + (seg >> 1) * 8) * WROW
                               + (seg & 1) * 8) * 2;

#pragma unroll 1
    for (int p = 0; p < 3; p++) {
        uint32_t abase = sb + (p == 2 ? MG_ALO : MG_AHI);
        uint32_t wbase = sb + (p == 1 ? MG_WLO : MG_WHI);
#pragma unroll
        for (int kb = 0; kb < 8; kb++) {
            uint32_t kadd = (uint32_t)(kb * 16) * 2;
            uint32_t a0[4], a1[4];
            ldsm_x4(a0[0], a0[1], a0[2], a0[3], abase + aoff + kadd);
            ldsm_x4(a1[0], a1[1], a1[2], a1[3],
                    abase + aoff + kadd + (uint32_t)(16 * WROW * 2));
            uint32_t b[4][2];
#pragma unroll
            for (int np = 0; np < 2; np++) {
                uint32_t r0, r1, r2, r3;
                ldsm_x4(r0, r1, r2, r3,
                        wbase + boff + kadd + (uint32_t)(np * 16 * WROW * 2));
                b[2 * np][0] = r0; b[2 * np][1] = r1;
                b[2 * np + 1][0] = r2; b[2 * np + 1][1] = r3;
            }
#pragma unroll
            for (int nb = 0; nb < 4; nb++) {
                mma_bf16(acc[0][nb], a0, b[nb][0], b[nb][1]);
                mma_bf16(acc[1][nb], a1, b[nb][0], b[nb][1]);
            }
        }
    }

#pragma unroll
    for (int m = 0; m < 2; m++) {
        int r_lo = row0 + mrow0 + m * 16 + (lane >> 2);
        int r_hi = r_lo + 8;
#pragma unroll
        for (int nb = 0; nb < 4; nb++) {
            int col = ncol0 + nb * 8 + (lane & 3) * 2;
            if (r_lo < n)
                *(__half2*)&Cout[(long long)r_lo * C + col] =
                    __floats2half2_rn(acc[m][nb][0], acc[m][nb][1]);
            if (r_hi < n)
                *(__half2*)&Cout[(long long)r_hi * C + col] =
                    __floats2half2_rn(acc[m][nb][2], acc[m][nb][3]);
        }
    }
}

// ---------------------------------------------------------------------------
// Fused GEMM2+GEMM3: out = relu(relu(agg+bc)@Wf^T + bf) @ W2^T + b2.
// CTA 128x128, 512 thr; h2 lives only in smem between the two MMA phases.
// ---------------------------------------------------------------------------
#define F_AHI  0
#define F_ALO  (F_AHI + W_IMG_B)
#define F_W1HI (F_ALO + W_IMG_B)
#define F_W1LO (F_W1HI + W_IMG_B)
#define F_W2HI (F_W1LO + W_IMG_B)
#define F_W2LO (F_W2HI + W_IMG_B)
#define F_SMEM (F_W2LO + W_IMG_B)                // 208896 bytes

__global__ __launch_bounds__(512, 1) void k_mgemm23(
    const float* __restrict__ A,
    const __nv_bfloat16* __restrict__ W1hi, const __nv_bfloat16* __restrict__ W1lo,
    const __nv_bfloat16* __restrict__ W2hi, const __nv_bfloat16* __restrict__ W2lo,
    const float* __restrict__ bc, const float* __restrict__ bf,
    const float* __restrict__ b2,
    float* __restrict__ Cout, int n) {
    extern __shared__ char smem[];
    uint32_t sb = smem_u32(smem);
    int tid = threadIdx.x;
    int wid = tid >> 5, lane = tid & 31;
    int row0 = blockIdx.x * 128;

    for (int i = tid; i < W_IMG_B / 16; i += 512) {
        cp_async16(sb + F_W1HI + i * 16, (const char*)W1hi + i * 16);
        cp_async16(sb + F_W1LO + i * 16, (const char*)W1lo + i * 16);
        cp_async16(sb + F_W2HI + i * 16, (const char*)W2hi + i * 16);
        cp_async16(sb + F_W2LO + i * 16, (const char*)W2lo + i * 16);
    }

    for (int idx = tid; idx < 4096; idx += 512) {
        int r = idx >> 5, q = idx & 31;
        int row = row0 + r, k0 = q * 4;
        float4 v = make_float4(0.f, 0.f, 0.f, 0.f);
        if (row < n) {
            v = *(const float4*)&A[(long long)row * C + k0];
            v.x = fmaxf(v.x + bc[k0 + 0], 0.0f);
            v.y = fmaxf(v.y + bc[k0 + 1], 0.0f);
            v.z = fmaxf(v.z + bc[k0 + 2], 0.0f);
            v.w = fmaxf(v.w + bc[k0 + 3], 0.0f);
        }
        uint32_t h01, l01, h23, l23;
        split2(v.x, v.y, h01, l01);
        split2(v.z, v.w, h23, l23);
        uint32_t off = (uint32_t)(r * WROW + k0) * 2;
        *(uint2*)(smem + F_AHI + off) = make_uint2(h01, h23);
        *(uint2*)(smem + F_ALO + off) = make_uint2(l01, l23);
    }
    cp_async_wait_all();
    __syncthreads();

    int mrow0 = (wid >> 2) * 32;        // 0,32,64,96
    int ncol0 = (wid & 3) * 32;         // 0,32,64,96
    int li = lane & 7, seg = lane >> 3;

    uint32_t aoff = (uint32_t)((mrow0 + li + (seg & 1) * 8) * WROW
                               + (seg >> 1) * 8) * 2;
    uint32_t boff = (uint32_t)((ncol0 + li + (seg >> 1) * 8) * WROW
                               + (seg & 1) * 8) * 2;

    float acc[2][4][4];

    // ---------------- phase 1: h2c = A-split @ Wf ----------------
#pragma unroll
    for (int m = 0; m < 2; m++)
#pragma unroll
        for (int nb = 0; nb < 4; nb++)
#pragma unroll
            for (int p = 0; p < 4; p++) acc[m][nb][p] = 0.0f;

#pragma unroll 1
    for (int p = 0; p < 3; p++) {
        uint32_t abase = sb + (p == 2 ? F_ALO : F_AHI);
        uint32_t wbase = sb + (p == 1 ? F_W1LO : F_W1HI);
#pragma unroll
        for (int kb = 0; kb < 8; kb++) {
            uint32_t kadd = (uint32_t)(kb * 16) * 2;
            uint32_t a0[4], a1[4];
            ldsm_x4(a0[0], a0[1], a0[2], a0[3], abase + aoff + kadd);
            ldsm_x4(a1[0], a1[1], a1[2], a1[3],
                    abase + aoff + kadd + (uint32_t)(16 * WROW * 2));
            uint32_t b[4][2];
#pragma unroll
            for (int np = 0; np < 2; np++) {
                uint32_t r0, r1, r2, r3;
                ldsm_x4(r0, r1, r2, r3,
                        wbase + boff + kadd + (uint32_t)(np * 16 * WROW * 2));
                b[2 * np][0] = r0; b[2 * np][1] = r1;
                b[2 * np + 1][0] = r2; b[2 * np + 1][1] = r3;
            }
#pragma unroll
            for (int nb = 0; nb < 4; nb++) {
                mma_bf16(acc[0][nb], a0, b[nb][0], b[nb][1]);
                mma_bf16(acc[1][nb], a1, b[nb][0], b[nb][1]);
            }
        }
    }
    __syncthreads();   // all phase-1 smem reads done before overwriting A

    // h2 = relu(acc + bf) -> bf16 hi/lo back into A smem (warp owns its patch)
    {
        float2 mb[4];
#pragma unroll
        for (int nb = 0; nb < 4; nb++) {
            int col = ncol0 + nb * 8 + (lane & 3) * 2;
            mb[nb] = *(const float2*)&bf[col];
        }
#pragma unroll
        for (int m = 0; m < 2; m++) {
            int r_lo = mrow0 + m * 16 + (lane >> 2);   // local rows
            int r_hi = r_lo + 8;
#pragma unroll
            for (int nb = 0; nb < 4; nb++) {
                int col = ncol0 + nb * 8 + (lane & 3) * 2;
                float x0 = fmaxf(acc[m][nb][0] + mb[nb].x, 0.0f);
                float y0 = fmaxf(acc[m][nb][1] + mb[nb].y, 0.0f);
                float x1 = fmaxf(acc[m][nb][2] + mb[nb].x, 0.0f);
                float y1 = fmaxf(acc[m][nb][3] + mb[nb].y, 0.0f);
                uint32_t h0, l0, h1, l1;
                split2(x0, y0, h0, l0);
                split2(x1, y1, h1, l1);
                uint32_t o0 = (uint32_t)(r_lo * WROW + col) * 2;
                uint32_t o1 = (uint32_t)(r_hi * WROW + col) * 2;
                *(uint32_t*)(smem + F_AHI + o0) = h0;
                *(uint32_t*)(smem + F_ALO + o0) = l0;
                *(uint32_t*)(smem + F_AHI + o1) = h1;
                *(uint32_t*)(smem + F_ALO + o1) = l1;
            }
        }
    }
    __syncthreads();

    // ---------------- phase 2: out = h2-split @ W2 ----------------
#pragma unroll
    for (int m = 0; m < 2; m++)
#pragma unroll
        for (int nb = 0; nb < 4; nb++)
#pragma unroll
            for (int p = 0; p < 4; p++) acc[m][nb][p] = 0.0f;

#pragma unroll 1
    for (int p = 0; p < 3; p++) {
        uint32_t abase = sb + (p == 2 ? F_ALO : F_AHI);
        uint32_t wbase = sb + (p == 1 ? F_W2LO : F_W2HI);
#pragma unroll
        for (int kb = 0; kb < 8; kb++) {
            uint32_t kadd = (uint32_t)(kb * 16) * 2;
            uint32_t a0[4], a1[4];
            ldsm_x4(a0[0], a0[1], a0[2], a0[3], abase + aoff + kadd);
            ldsm_x4(a1[0], a1[1], a1[2], a1[3],
                    abase + aoff + kadd + (uint32_t)(16 * WROW * 2));
            uint32_t b[4][2];
#pragma unroll
            for (int np = 0; np < 2; np++) {
                uint32_t r0, r1, r2, r3;
                ldsm_x4(r0, r1, r2, r3,
                        wbase + boff + kadd + (uint32_t)(np * 16 * WROW * 2));
                b[2 * np][0] = r0; b[2 * np][1] = r1;
                b[2 * np + 1][0] = r2; b[2 * np + 1][1] = r3;
            }
#pragma unroll
            for (int nb = 0; nb < 4; nb++) {
                mma_bf16(acc[0][nb], a0, b[nb][0], b[nb][1]);
                mma_bf16(acc[1][nb], a1, b[nb][0], b[nb][1]);
            }
        }
    }

    // final epilogue: + b2, store to global
    {
        float2 pb[4];
#pragma unroll
        for (int nb = 0; nb < 4; nb++) {
            int col = ncol0 + nb * 8 + (lane & 3) * 2;
            pb[nb] = *(const float2*)&b2[col];
        }
#pragma unroll
        for (int m = 0; m < 2; m++) {
            int r_lo = row0 + mrow0 + m * 16 + (lane >> 2);
            int r_hi = r_lo + 8;
#pragma unroll
            for (int nb = 0; nb < 4; nb++) {
                int col = ncol0 + nb * 8 + (lane & 3) * 2;
                if (r_lo < n) *(float2*)&Cout[(long long)r_lo * C + col] =
                    make_float2(acc[m][nb][0] + pb[nb].x, acc[m][nb][1] + pb[nb].y);
                if (r_hi < n) *(float2*)&Cout[(long long)r_hi * C + col] =
                    make_float2(acc[m][nb][2] + pb[nb].x, acc[m][nb][3] + pb[nb].y);
            }
        }
    }
}

// ---------------------------------------------------------------------------
extern "C" void kernel_launch(void* const* d_in, const int* in_sizes, int n_in,
                              void* d_out, int out_size) {
    const float* x  = (const float*)d_in[0];
    const void*  ei = d_in[1];
    const float* ew = (const float*)d_in[2];
    const float* Wc = (const float*)d_in[3];
    const float* bc = (const float*)d_in[4];
    const float* Wf = (const float*)d_in[5];
    const float* bf = (const float*)d_in[6];
    const float* W2 = (const float*)d_in[7];
    const float* b2 = (const float*)d_in[8];
    float* out = (float*)d_out;

    int n = in_sizes[0] / C;
    long long E = in_sizes[2];
    int nb = (n + 255) / 256;
    int g1_blocks = (n + 63) / 64;
    int g23_blocks = (n + 127) / 128;
    unsigned eblocks = (unsigned)((E + 255) / 256);

    cudaFuncSetAttribute(k_mgemm1,
                         cudaFuncAttributeMaxDynamicSharedMemorySize, MG_SMEM);
    cudaFuncSetAttribute(k_mgemm23,
                         cudaFuncAttributeMaxDynamicSharedMemorySize, F_SMEM);

    __half* g_h_p;  cudaGetSymbolAddress((void**)&g_h_p,   g_h);
    float* g_agg_p; cudaGetSymbolAddress((void**)&g_agg_p, g_agg);
    __nv_bfloat16* g_Wimg_p;
    cudaGetSymbolAddress((void**)&g_Wimg_p, g_Wimg);
    const int IMG_E = 128 * WROW;
    const __nv_bfloat16* WcHi = g_Wimg_p;
    const __nv_bfloat16* WcLo = g_Wimg_p + IMG_E;
    const __nv_bfloat16* WfHi = g_Wimg_p + 2 * IMG_E;
    const __nv_bfloat16* WfLo = g_Wimg_p + 3 * IMG_E;
    const __nv_bfloat16* W2Hi = g_Wimg_p + 4 * IMG_E;
    const __nv_bfloat16* W2Lo = g_Wimg_p + 5 * IMG_E;

    // 1. zero scratch + dtype detect
    k_pre0<<<nb, 256>>>((const unsigned int*)ei, n, E);
    // 2. bf16-split weight images + edge_weight==1 check
    k_prep<<<192 + 512, 256>>>(Wc, Wf, W2, ew, E);
    // 3. per-dst counts (+conditional weighted degree)
    k_cnt<<<eblocks, 256>>>(ei, ew, E);
    // 4. h = x @ Wc^T (fp16 out)   <-- 4th launch: ncu profiles this one
    k_mgemm1<<<g1_blocks, 256, MG_SMEM>>>(x, WcHi, WcLo, g_h_p, n);
    // 5-7. exclusive prefix sum (+dinv fused)
    k_scanA<<<nb, 256>>>(n);
    k_scanB<<<1, 512>>>(nb);
    k_scanC<<<nb, 256>>>(n);
    // 8. scatter edges into dst buckets
    k_scatter<<<eblocks, 256>>>(ei, ew, E);
    // 9. atomic-free gather over fp16 h (includes self-loop term)
    k_gather<<<(n * 32 + 255) / 256, 256>>>(n);
    // 10. fused: out = relu(relu(agg+bc)@Wf^T + bf) @ W2^T + b2
    k_mgemm23<<<g23_blocks, 512, F_SMEM>>>(
        g_agg_p, WfHi, WfLo, W2Hi, W2Lo, bc, bf, b2, out, n);
}